// round 17
// baseline (speedup 1.0000x reference)
#include <cuda_runtime.h>
#include <math.h>
#include <stdint.h>

#define MTOT 8192
#define CDIM 1024
#define NHEAD 16
#define DH 64
#define TSEQ 2048

// Scratch (allocation-free rule: __device__ globals)
__device__ float g_Xp [(size_t)MTOT * CDIM];   // x  in A-fragment layout (tf32)
__device__ float g_Op [(size_t)MTOT * CDIM];   // attn out, A-fragment layout
__device__ float g_Qa [(size_t)MTOT * CDIM];   // Q  as attn A-frags [bh][t16][ks][lane][4]
__device__ float g_Kb [(size_t)MTOT * CDIM];   // Q  as attn B-frags (keys)
__device__ float g_Vb [(size_t)MTOT * CDIM];   // V  as attn B-frags (n=dh,k=key)
__device__ float g_Wqp[(size_t)CDIM * CDIM];   // weights in B-fragment layout
__device__ float g_Wvp[(size_t)CDIM * CDIM];
__device__ float g_Wop[(size_t)CDIM * CDIM];

__device__ __forceinline__ float f2tf32f(float v) {
    uint32_t r;
    asm("cvt.rna.tf32.f32 %0, %1;" : "=r"(r) : "f"(v));
    return __uint_as_float(r);
}
__device__ __forceinline__ uint32_t f2tf32u(float v) {
    uint32_t r;
    asm("cvt.rna.tf32.f32 %0, %1;" : "=r"(r) : "f"(v));
    return r;
}

#define MMA_TF32(acc, a, b)                                                    \
    asm volatile(                                                              \
        "mma.sync.aligned.m16n8k8.row.col.f32.tf32.tf32.f32 "                  \
        "{%0,%1,%2,%3}, {%4,%5,%6,%7}, {%8,%9}, {%0,%1,%2,%3};"                \
        : "+f"((acc)[0]), "+f"((acc)[1]), "+f"((acc)[2]), "+f"((acc)[3])       \
        : "r"((a)[0]), "r"((a)[1]), "r"((a)[2]), "r"((a)[3]),                  \
          "r"((b).x), "r"((b).y))

// ===========================================================================
// GEMM fragment layouts (128-row/col blocks, 32 chunks of K=32) — as R15:
//  A: [mblock][chunk][(mt*4+ks)*32+lane]*4+reg
//  B: [nblock][chunk][(nt*4+ks)*32+lane]*2+reg
// Attention fragment layouts:
//  Qa: [bh][t16(128)][ks(8)][lane(32)][reg(4)]   (m=t&15, k=d)
//  Kb: [bh][kt64(32)][nt(8)][ks(8)][lane(32)][reg(2)]  (n=key, k=d)
//  Vb: [bh][kt64(32)][nt(8)][ks(8)][lane(32)][reg(2)]  (n=d, k=key)
// ===========================================================================

__global__ __launch_bounds__(256) void perm_w(
    const float* __restrict__ W, float* __restrict__ Wp)
{
    int g = blockIdx.x * 256 + threadIdx.x;
    int n = g >> 8;
    int k = (g & 255) << 2;
    float4 w4 = *(const float4*)(W + (size_t)n * CDIM + k);
    int cb = n >> 7, chunk = k >> 5, ks = (k >> 3) & 3, regHi = (k >> 2) & 1;
    int nt = (n >> 3) & 15, nn = n & 7;
    float* d = Wp + ((size_t)(cb * 32 + chunk)) * 4096
                 + ((((nt * 4 + ks) * 32) + (nn << 2)) << 1) + regHi;
    d[0] = f2tf32f(w4.x); d[2] = f2tf32f(w4.y);
    d[4] = f2tf32f(w4.z); d[6] = f2tf32f(w4.w);
}

__global__ __launch_bounds__(256) void perm_x(
    const float* __restrict__ X, float* __restrict__ Xp)
{
    int g = blockIdx.x * 256 + threadIdx.x;
    int row = g >> 8;
    int k = (g & 255) << 2;
    float4 a4 = *(const float4*)(X + (size_t)row * CDIM + k);
    int mtile = row >> 7, r = row & 127, mt = r >> 4, rm = r & 15;
    int chunk = k >> 5, ks = (k >> 3) & 3, regHi = (k >> 2) & 1;
    float* d = Xp + ((size_t)(mtile * 32 + chunk)) * 4096
                 + ((((mt * 4 + ks) * 32) + ((rm & 7) << 2)) << 2)
                 + ((rm >> 3) | (regHi << 1));
    d[0] = f2tf32f(a4.x); d[4]  = f2tf32f(a4.y);
    d[8] = f2tf32f(a4.z); d[12] = f2tf32f(a4.w);
}

// ===========================================================================
// Zero-smem fragment-streaming GEMM (R15 core).  mode:
//   0: write C row-major (final O-projection)
//   1: scatter into Qa + Kb (Q projection; K == Q per reference bug)
//   2: scatter into Vb     (V projection)
// ===========================================================================
__global__ __launch_bounds__(256, 2) void gemm_frag(
    const float* __restrict__ Ap, const float* __restrict__ Bp,
    float* __restrict__ C, float* __restrict__ Fa, float* __restrict__ Fb,
    int mode)
{
    const int tid = threadIdx.x;
    const int lane = tid & 31;
    const int wid = tid >> 5;
    const int wm = wid & 1;
    const int wn = wid >> 1;

    const float* Abase = Ap + (size_t)blockIdx.y * 32 * 4096;
    const float* Bbase = Bp + (size_t)blockIdx.x * 32 * 4096;

    float acc[4][4][4];
#pragma unroll
    for (int i = 0; i < 4; i++)
#pragma unroll
        for (int j = 0; j < 4; j++)
#pragma unroll
            for (int r = 0; r < 4; r++) acc[i][j][r] = 0.f;

    for (int c = 0; c < 32; c++) {
        const float* Ac = Abase + (size_t)c * 4096;
        const float* Bc = Bbase + (size_t)c * 4096;
#pragma unroll
        for (int ks = 0; ks < 4; ks++) {
            uint4 af[4]; uint2 bf[4];
#pragma unroll
            for (int i = 0; i < 4; i++)
                af[i] = *(const uint4*)&Ac[(((wm * 16 + i * 4 + ks) * 32 + lane) << 2)];
#pragma unroll
            for (int j = 0; j < 4; j++)
                bf[j] = *(const uint2*)&Bc[(((wn * 16 + j * 4 + ks) * 32 + lane) << 1)];
#pragma unroll
            for (int i = 0; i < 4; i++)
#pragma unroll
                for (int j = 0; j < 4; j++)
                    asm volatile(
                        "mma.sync.aligned.m16n8k8.row.col.f32.tf32.tf32.f32 "
                        "{%0,%1,%2,%3}, {%4,%5,%6,%7}, {%8,%9}, {%0,%1,%2,%3};"
                        : "+f"(acc[i][j][0]), "+f"(acc[i][j][1]),
                          "+f"(acc[i][j][2]), "+f"(acc[i][j][3])
                        : "r"(af[i].x), "r"(af[i].y), "r"(af[i].z), "r"(af[i].w),
                          "r"(bf[j].x), "r"(bf[j].y));
        }
    }

    const int grp = lane >> 2, tig = lane & 3;
    const int row0 = blockIdx.y * 128, col0 = blockIdx.x * 128;

    if (mode == 0) {
#pragma unroll
        for (int i = 0; i < 4; i++) {
            int r = row0 + wm * 64 + i * 16 + grp;
#pragma unroll
            for (int j = 0; j < 4; j++) {
                int cc = col0 + wn * 32 + j * 8 + (tig << 1);
                *(float2*)(C + (size_t)r * CDIM + cc) =
                    make_float2(acc[i][j][0], acc[i][j][1]);
                *(float2*)(C + (size_t)(r + 8) * CDIM + cc) =
                    make_float2(acc[i][j][2], acc[i][j][3]);
            }
        }
        return;
    }

    // Fragment-scatter epilogues
#pragma unroll
    for (int i = 0; i < 4; i++) {
#pragma unroll
        for (int j = 0; j < 4; j++) {
#pragma unroll
            for (int rh = 0; rh < 2; rh++) {        // rh: row half (grp / grp+8)
#pragma unroll
                for (int e = 0; e < 2; e++) {       // e: col element
                    int rr = row0 + wm * 64 + i * 16 + grp + rh * 8;
                    int ccc = col0 + wn * 32 + j * 8 + (tig << 1) + e;
                    float val = f2tf32f(acc[i][j][rh * 2 + e]);
                    int bb = rr >> 11, t = rr & 2047;
                    int h = ccc >> 6, d = ccc & 63;
                    int bh = (bb << 4) + h;
                    if (mode == 1) {
                        // Qa: A-frag (m = t&15, k = d)
                        size_t qi = ((((size_t)bh * 128 + (t >> 4)) * 8 + (d >> 3)) << 7)
                                  + (((t & 7) << 2) + (d & 3)) * 4
                                  + ((t >> 3) & 1) + (((d >> 2) & 1) << 1);
                        Fa[qi] = val;
                        // Kb: B-frag (n = key t, k = d)
                        size_t ki = ((((size_t)bh * 32 + (t >> 6)) * 8 + ((t >> 3) & 7)) * 8
                                     + (d >> 3)) * 64
                                  + (((t & 7) << 2) + (d & 3)) * 2 + ((d >> 2) & 1);
                        Fb[ki] = val;
                    } else {
                        // Vb: B-frag (n = d, k = key t)
                        size_t vi = ((((size_t)bh * 32 + (t >> 6)) * 8 + (d >> 3)) * 8
                                     + ((t >> 3) & 7)) * 64
                                  + (((d & 7) << 2) + (t & 3)) * 2 + ((t >> 2) & 1);
                        Fb[vi] = val;
                    }
                }
            }
        }
    }
}

// ===========================================================================
// Fragment-streaming flash attention: NO smem, NO barriers, NO conversions.
// CTA = 128 queries (8 independent warps, 16 rows each); 64-key tiles.
// All operands read as ready-made m16n8k8 fragments from Qa/Kb/Vb.
// Each warp loops only to its own causal bound. Output -> g_Op (A-frag).
// ===========================================================================
__global__ __launch_bounds__(256, 2) void attn_frag(
    const float* __restrict__ Qa, const float* __restrict__ Kb,
    const float* __restrict__ Vb, float* __restrict__ Op)
{
    const int tid = threadIdx.x;
    const int lane = tid & 31, w = tid >> 5;
    const int grp = lane >> 2, tig = lane & 3;
    const int qb = (int)gridDim.x - 1 - (int)blockIdx.x;  // longest first
    const int bh = blockIdx.y;
    const int b = bh >> 4, h = bh & 15;
    const int t0 = qb * 128;

    const int row0g = t0 + w * 16 + grp;    // in-sequence query row
    const int row1g = row0g + 8;

    // ---- Q A-fragments: one uint4 per k-step ----
    uint32_t qa[8][4];
    {
        const float* Qw = Qa + (((size_t)bh * 128 + (t0 >> 4) + w) << 10);
#pragma unroll
        for (int ks = 0; ks < 8; ks++) {
            uint4 v = *(const uint4*)&Qw[(ks << 7) + (lane << 2)];
            qa[ks][0] = v.x; qa[ks][1] = v.y; qa[ks][2] = v.z; qa[ks][3] = v.w;
        }
    }

    float oacc[8][4];
#pragma unroll
    for (int nt = 0; nt < 8; nt++)
#pragma unroll
        for (int r = 0; r < 4; r++) oacc[nt][r] = 0.f;
    float m0 = -1e30f, m1 = -1e30f, l0 = 0.f, l1 = 0.f;

    const float scale = 0.125f;   // 1/sqrt(64)
    const float* Kbh = Kb + ((size_t)bh << 17);   // 32 tiles * 4096
    const float* Vbh = Vb + ((size_t)bh << 17);
    const int ntw = ((t0 + w * 16 + 15) >> 6) + 1;   // this warp's causal bound

    for (int jt = 0; jt < ntw; jt++) {
        const int j0 = jt * 64;
        const float* Kt = Kbh + (size_t)jt * 4096;
        const float* Vt = Vbh + (size_t)jt * 4096;

        // ---- S = Q K^T ----
        float sc[8][4];
#pragma unroll
        for (int nt = 0; nt < 8; nt++) {
            sc[nt][0] = 0.f; sc[nt][1] = 0.f; sc[nt][2] = 0.f; sc[nt][3] = 0.f;
#pragma unroll
            for (int ks = 0; ks < 8; ks++) {
                uint2 kb = *(const uint2*)&Kt[((nt * 8 + ks) << 6) + (lane << 1)];
                MMA_TF32(sc[nt], qa[ks], kb);
            }
        }

        // ---- scale + causal mask ----
#pragma unroll
        for (int nt = 0; nt < 8; nt++) {
            sc[nt][0] *= scale; sc[nt][1] *= scale;
            sc[nt][2] *= scale; sc[nt][3] *= scale;
        }
        if (j0 + 63 > row0g) {
#pragma unroll
            for (int nt = 0; nt < 8; nt++) {
                int c = j0 + nt * 8 + (tig << 1);
                if (c > row0g)     sc[nt][0] = -1e30f;
                if (c + 1 > row0g) sc[nt][1] = -1e30f;
                if (c > row1g)     sc[nt][2] = -1e30f;
                if (c + 1 > row1g) sc[nt][3] = -1e30f;
            }
        }

        // ---- online softmax (rows in lane quads) ----
        float mx0 = -1e30f, mx1 = -1e30f;
#pragma unroll
        for (int nt = 0; nt < 8; nt++) {
            mx0 = fmaxf(mx0, fmaxf(sc[nt][0], sc[nt][1]));
            mx1 = fmaxf(mx1, fmaxf(sc[nt][2], sc[nt][3]));
        }
        mx0 = fmaxf(mx0, __shfl_xor_sync(0xffffffffu, mx0, 1));
        mx0 = fmaxf(mx0, __shfl_xor_sync(0xffffffffu, mx0, 2));
        mx1 = fmaxf(mx1, __shfl_xor_sync(0xffffffffu, mx1, 1));
        mx1 = fmaxf(mx1, __shfl_xor_sync(0xffffffffu, mx1, 2));

        float mn0 = fmaxf(m0, mx0), mn1 = fmaxf(m1, mx1);
        float al0 = __expf(m0 - mn0), al1 = __expf(m1 - mn1);
        m0 = mn0; m1 = mn1;

        float ps0 = 0.f, ps1 = 0.f;
#pragma unroll
        for (int nt = 0; nt < 8; nt++) {
            sc[nt][0] = __expf(sc[nt][0] - mn0);
            sc[nt][1] = __expf(sc[nt][1] - mn0);
            sc[nt][2] = __expf(sc[nt][2] - mn1);
            sc[nt][3] = __expf(sc[nt][3] - mn1);
            ps0 += sc[nt][0] + sc[nt][1];
            ps1 += sc[nt][2] + sc[nt][3];
        }
        ps0 += __shfl_xor_sync(0xffffffffu, ps0, 1);
        ps0 += __shfl_xor_sync(0xffffffffu, ps0, 2);
        ps1 += __shfl_xor_sync(0xffffffffu, ps1, 1);
        ps1 += __shfl_xor_sync(0xffffffffu, ps1, 2);
        l0 = l0 * al0 + ps0;
        l1 = l1 * al1 + ps1;

#pragma unroll
        for (int nt = 0; nt < 8; nt++) {
            oacc[nt][0] *= al0; oacc[nt][1] *= al0;
            oacc[nt][2] *= al1; oacc[nt][3] *= al1;
        }

        // ---- O += P V  (P S-frag -> A-frag via width-4 shuffles) ----
        const int sL = tig >> 1;
        const bool odd = tig & 1;
#pragma unroll
        for (int ks = 0; ks < 8; ks++) {
            float a0 = __shfl_sync(0xffffffffu, sc[ks][0], sL, 4);
            float a1 = __shfl_sync(0xffffffffu, sc[ks][1], sL, 4);
            float b0 = __shfl_sync(0xffffffffu, sc[ks][0], sL + 2, 4);
            float b1 = __shfl_sync(0xffffffffu, sc[ks][1], sL + 2, 4);
            float c0 = __shfl_sync(0xffffffffu, sc[ks][2], sL, 4);
            float c1 = __shfl_sync(0xffffffffu, sc[ks][3], sL, 4);
            float d0 = __shfl_sync(0xffffffffu, sc[ks][2], sL + 2, 4);
            float d1 = __shfl_sync(0xffffffffu, sc[ks][3], sL + 2, 4);
            uint32_t pa[4];
            pa[0] = f2tf32u(odd ? a1 : a0);
            pa[1] = f2tf32u(odd ? c1 : c0);
            pa[2] = f2tf32u(odd ? b1 : b0);
            pa[3] = f2tf32u(odd ? d1 : d0);
#pragma unroll
            for (int nt = 0; nt < 8; nt++) {
                uint2 vb = *(const uint2*)&Vt[((nt * 8 + ks) << 6) + (lane << 1)];
                MMA_TF32(oacc[nt], pa, vb);
            }
        }
    }

    // ---- epilogue: write O in GEMM A-fragment layout (tf32) ----
    float inv0 = 1.f / l0, inv1 = 1.f / l1;
    const int growA = b * TSEQ + row0g;
    const int growB = b * TSEQ + row1g;
    const int mtA = (growA & 127) >> 4, rmA = growA & 15;
    const int mtB = (growB & 127) >> 4, rmB = growB & 15;
    const size_t blkA = (size_t)(growA >> 7) * 32 * 4096;
    const size_t blkB = (size_t)(growB >> 7) * 32 * 4096;
#pragma unroll
    for (int nt = 0; nt < 8; nt++) {
        int col = h * DH + nt * 8 + (tig << 1);
        int chunk = col >> 5, ks = (col >> 3) & 3, e = col & 3;
        int regHi = (col >> 2) & 1;
        size_t iA = blkA + (size_t)chunk * 4096
                  + (((mtA * 4 + ks) * 32 + ((rmA & 7) << 2) + e) << 2)
                  + ((rmA >> 3) | (regHi << 1));
        size_t iB = blkB + (size_t)chunk * 4096
                  + (((mtB * 4 + ks) * 32 + ((rmB & 7) << 2) + e) << 2)
                  + ((rmB >> 3) | (regHi << 1));
        Op[iA]     = f2tf32f(oacc[nt][0] * inv0);
        Op[iA + 4] = f2tf32f(oacc[nt][1] * inv0);
        Op[iB]     = f2tf32f(oacc[nt][2] * inv1);
        Op[iB + 4] = f2tf32f(oacc[nt][3] * inv1);
    }
}

// ---------------------------------------------------------------------------
extern "C" void kernel_launch(void* const* d_in, const int* in_sizes, int n_in,
                              void* d_out, int out_size)
{
    (void)in_sizes; (void)n_in; (void)out_size;
    const float* x  = (const float*)d_in[0];
    const float* Wq = (const float*)d_in[1];
    // d_in[2] (W_k) intentionally unused: reference computes K with W_q
    const float* Wv = (const float*)d_in[3];
    const float* Wo = (const float*)d_in[4];
    float* out = (float*)d_out;

    float *Xp, *Op, *Qa, *Kbp, *Vbp, *Wqp, *Wvp, *Wop;
    cudaGetSymbolAddress((void**)&Xp,  g_Xp);
    cudaGetSymbolAddress((void**)&Op,  g_Op);
    cudaGetSymbolAddress((void**)&Qa,  g_Qa);
    cudaGetSymbolAddress((void**)&Kbp, g_Kb);
    cudaGetSymbolAddress((void**)&Vbp, g_Vb);
    cudaGetSymbolAddress((void**)&Wqp, g_Wqp);
    cudaGetSymbolAddress((void**)&Wvp, g_Wvp);
    cudaGetSymbolAddress((void**)&Wop, g_Wop);

    // Pre-permute operands into fragment layouts (tf32)
    perm_w<<<1024, 256>>>(Wq, Wqp);
    perm_w<<<1024, 256>>>(Wv, Wvp);
    perm_w<<<1024, 256>>>(Wo, Wop);
    perm_x<<<8192, 256>>>(x, Xp);

    dim3 gg(CDIM / 128, MTOT / 128);  // (8, 64)
    gemm_frag<<<gg, 256>>>(Xp, Wqp, nullptr, Qa, Kbp, 1);   // Q proj -> Qa + Kb
    gemm_frag<<<gg, 256>>>(Xp, Wvp, nullptr, nullptr, Vbp, 2); // V proj -> Vb

    attn_frag<<<dim3(TSEQ / 128, 4 * NHEAD), 256>>>(Qa, Kbp, Vbp, Op);

    gemm_frag<<<gg, 256>>>(Op, Wop, out, nullptr, nullptr, 0); // O proj
}